// round 15
// baseline (speedup 1.0000x reference)
#include <cuda_runtime.h>
#include <cuda_bf16.h>
#include <cstdint>
#include <cstddef>
#include <math.h>

typedef unsigned int u32;

#define Nn 8
#define Cc 128
#define Hh 112
#define Ww 112
#define HW (Hh*Ww)          /* 12544 */
#define CHW (Cc*HW)         /* 1605632 */
#define NTOT (Nn*CHW)       /* 12845056 */
#define T2T_ROW 116
#define T2T_H (T2T_ROW*Cc)  /* 14848 per (n,h) */

// ---- global scratch ----
__device__ float g_t3[NTOT];
__device__ __nv_bfloat16 g_t4r[NTOT];                  // t4 rolled+transposed [n][h][w'][c]
__device__ float g_t5[Nn*Cc*Cc];
__device__ __nv_bfloat16 g_t2Th[(size_t)Nn*Hh*T2T_H];  // silu transposed [n][h][w'][c] hi
__device__ __nv_bfloat16 g_t2Tl[(size_t)Nn*Hh*T2T_H];  // lo
__device__ __nv_bfloat16 g_sgh[NTOT];                  // sigmoid(x) [n][c][s] hi
__device__ __nv_bfloat16 g_sgl[NTOT];                  // lo
__device__ __nv_bfloat16 g_w3h[3*Cc*Cc];               // [kk][o][i]
__device__ __nv_bfloat16 g_weffb[Cc*224];              // t15 fused W [o][k*32+cc]
__device__ __nv_bfloat16 g_amh[Nn*Cc*Cc];              // t14 A [n][d][c] hi
__device__ __nv_bfloat16 g_aml[Nn*Cc*Cc];

// ---- helpers ----
__device__ __forceinline__ u32 smem_u32(const void* p) {
    return (u32)__cvta_generic_to_shared(p);
}
__device__ __forceinline__ void ldsm4(u32& r0, u32& r1, u32& r2, u32& r3, u32 a) {
    asm volatile("ldmatrix.sync.aligned.m8n8.x4.shared.b16 {%0,%1,%2,%3},[%4];\n"
                 : "=r"(r0), "=r"(r1), "=r"(r2), "=r"(r3) : "r"(a));
}
__device__ __forceinline__ void ldsm2(u32& r0, u32& r1, u32 a) {
    asm volatile("ldmatrix.sync.aligned.m8n8.x2.shared.b16 {%0,%1},[%2];\n"
                 : "=r"(r0), "=r"(r1) : "r"(a));
}
__device__ __forceinline__ void mma16816(float* c, u32 a0, u32 a1, u32 a2, u32 a3,
                                         u32 b0, u32 b1) {
    asm volatile("mma.sync.aligned.m16n8k16.row.col.f32.bf16.bf16.f32 "
                 "{%0,%1,%2,%3},{%4,%5,%6,%7},{%8,%9},{%0,%1,%2,%3};\n"
                 : "+f"(c[0]), "+f"(c[1]), "+f"(c[2]), "+f"(c[3])
                 : "r"(a0), "r"(a1), "r"(a2), "r"(a3), "r"(b0), "r"(b1));
}
__device__ __forceinline__ void bsplit(float v, __nv_bfloat16& hi, __nv_bfloat16& lo) {
    hi = __float2bfloat16(v);
    lo = __float2bfloat16(v - __bfloat162float(hi));
}
__device__ __forceinline__ u32 pk(__nv_bfloat16 a, __nv_bfloat16 b) {
    return (u32)__bfloat16_as_ushort(a) | ((u32)__bfloat16_as_ushort(b) << 16);
}

// ---------------------------------------------------------------------------
// K1: silu(x) -> t2T bf16 hi/lo; sigmoid(x) hi/lo [n][c][s]; embedded prep
// ---------------------------------------------------------------------------
__global__ void __launch_bounds__(256) k_silu_t(const float* __restrict__ x,
                                                const float* __restrict__ w3,
                                                const float* __restrict__ w10,
                                                const float* __restrict__ w15) {
    extern __shared__ float ys[];   // [116][129]
    int h = blockIdx.x, n = blockIdx.y, tid = threadIdx.x;
    if (h == 0) {
        float* t5b = g_t5 + n * 16384;
        for (int i = tid; i < 16384; i += 256) t5b[i] = 0.f;
    }
    if (h == 1 && n == 0) {
        for (int i = tid; i < 3 * 128 * 128; i += 256) {
            int ii = i & 127, o = (i >> 7) & 127, kk = i >> 14;
            g_w3h[i] = __float2bfloat16(w3[o * 384 + ii * 3 + kk]);
        }
        for (int i = tid; i < 128 * 224; i += 256) {
            int q = i % 224, o = i / 224;
            int k = q >> 5, cc = q & 31;
            int cabs = ((o >> 5) << 5) + cc;
            g_weffb[i] = __float2bfloat16(w15[o * 224 + cc * 7 + k] * w10[cabs * 7 + k]);
        }
    }
    for (int i = tid; i < 4 * 128; i += 256) {
        int r = i >> 7, c = i & 127;
        int wp = (r < 2) ? r : (112 + r);
        ys[wp * 129 + c] = 0.f;
    }
    const float* xr = x + (size_t)n * CHW + (size_t)h * Ww;
    for (int i = tid; i < 128 * 28; i += 256) {
        int c = i / 28, wq = i % 28;
        float4 v = *reinterpret_cast<const float4*>(xr + (size_t)c * HW + 4 * wq);
        float u[4] = {v.x, v.y, v.z, v.w};
        __nv_bfloat16 sh[4], sl[4];
        #pragma unroll
        for (int j = 0; j < 4; j++) {
            float s = 1.f / (1.f + __expf(-u[j]));
            bsplit(s, sh[j], sl[j]);
            ys[(4 * wq + j + 2) * 129 + c] = u[j] * s;
        }
        size_t so = (size_t)n * CHW + (size_t)c * HW + (size_t)h * Ww + 4 * wq;
        *reinterpret_cast<uint2*>(g_sgh + so) = make_uint2(pk(sh[0], sh[1]), pk(sh[2], sh[3]));
        *reinterpret_cast<uint2*>(g_sgl + so) = make_uint2(pk(sl[0], sl[1]), pk(sl[2], sl[3]));
    }
    __syncthreads();
    size_t base = ((size_t)(n * Hh + h)) * T2T_H;
    for (int i = tid; i < T2T_H / 8; i += 256) {
        int wp = i >> 4, c8 = (i & 15) * 8;
        const float* src = ys + wp * 129 + c8;
        u32 hw[4], lw[4];
        #pragma unroll
        for (int j = 0; j < 4; j++) {
            __nv_bfloat16 h0, l0, h1, l1;
            bsplit(src[2 * j], h0, l0);
            bsplit(src[2 * j + 1], h1, l1);
            hw[j] = pk(h0, h1);
            lw[j] = pk(l0, l1);
        }
        *reinterpret_cast<uint4*>(g_t2Th + base + (size_t)i * 8) = make_uint4(hw[0], hw[1], hw[2], hw[3]);
        *reinterpret_cast<uint4*>(g_t2Tl + base + (size_t)i * 8) = make_uint4(lw[0], lw[1], lw[2], lw[3]);
    }
}

// ---------------------------------------------------------------------------
// K3: t5 (bf16x3; A = precomputed sigmoid copy, B = bsplit(x))
// ---------------------------------------------------------------------------
__global__ void __launch_bounds__(256) k_t5(const float* __restrict__ x) {
    extern __shared__ __nv_bfloat16 sm5[];
    __nv_bfloat16* sAh = sm5;
    __nv_bfloat16* sAl = sm5 + 128 * 72;
    __nv_bfloat16* sBh = sm5 + 2 * 128 * 72;
    __nv_bfloat16* sBl = sm5 + 3 * 128 * 72;
    int n = blockIdx.y, tid = threadIdx.x, lane = tid & 31, warp = tid >> 5;
    int wm = warp >> 2, wn = warp & 3;
    int s0 = blockIdx.x * 448;
    const float* xb = x + (size_t)n * CHW;
    const __nv_bfloat16* sgh = g_sgh + (size_t)n * CHW;
    const __nv_bfloat16* sgl = g_sgl + (size_t)n * CHW;

    float acc[4][4][4];
    #pragma unroll
    for (int a = 0; a < 4; a++)
        #pragma unroll
        for (int b = 0; b < 4; b++)
            #pragma unroll
            for (int c = 0; c < 4; c++) acc[a][b][c] = 0.f;

    int qa_row = (lane & 7) + ((lane >> 3) & 1) * 8;
    int qa_col = (lane >> 4) * 8;
    int lb = lane & 15;
    int qb_row = lb & 7, qb_col = (lb >> 3) * 8;
    u32 aH = smem_u32(sAh), aL = smem_u32(sAl), bH = smem_u32(sBh), bL = smem_u32(sBl);

    for (int st = 0; st < 7; st++) {
        int sb = s0 + st * 64;
        __syncthreads();
        for (int i = tid; i < 128 * 8; i += 256) {
            int c = i >> 3, q = i & 7;
            *reinterpret_cast<uint4*>(sAh + c * 72 + q * 8) =
                *reinterpret_cast<const uint4*>(sgh + (size_t)c * HW + sb + q * 8);
            *reinterpret_cast<uint4*>(sAl + c * 72 + q * 8) =
                *reinterpret_cast<const uint4*>(sgl + (size_t)c * HW + sb + q * 8);
        }
        for (int i = tid; i < 128 * 16; i += 256) {
            int c = i >> 4, q = i & 15;
            float4 v = *reinterpret_cast<const float4*>(xb + (size_t)c * HW + sb + 4 * q);
            float u[4] = {v.x, v.y, v.z, v.w};
            __nv_bfloat16 bh0, bl0, bh1, bl1;
            int idx = c * 72 + 4 * q;
            bsplit(u[0], bh0, bl0); bsplit(u[1], bh1, bl1);
            u32 b01 = pk(bh0, bh1), b01l = pk(bl0, bl1);
            bsplit(u[2], bh0, bl0); bsplit(u[3], bh1, bl1);
            *reinterpret_cast<uint2*>(sBh + idx) = make_uint2(b01, pk(bh0, bh1));
            *reinterpret_cast<uint2*>(sBl + idx) = make_uint2(b01l, pk(bl0, bl1));
        }
        __syncthreads();
        #pragma unroll
        for (int k0 = 0; k0 < 64; k0 += 16) {
            u32 ah[4][4], al[4][4], bh[4][2], bl[4][2];
            #pragma unroll
            for (int mt = 0; mt < 4; mt++) {
                u32 off = (u32)(((wm * 64 + mt * 16 + qa_row) * 72 + k0 + qa_col) * 2);
                ldsm4(ah[mt][0], ah[mt][1], ah[mt][2], ah[mt][3], aH + off);
                ldsm4(al[mt][0], al[mt][1], al[mt][2], al[mt][3], aL + off);
            }
            #pragma unroll
            for (int nt = 0; nt < 4; nt++) {
                u32 off = (u32)(((wn * 32 + nt * 8 + qb_row) * 72 + k0 + qb_col) * 2);
                ldsm2(bh[nt][0], bh[nt][1], bH + off);
                ldsm2(bl[nt][0], bl[nt][1], bL + off);
            }
            #pragma unroll
            for (int mt = 0; mt < 4; mt++) {
                #pragma unroll
                for (int nt = 0; nt < 4; nt++) {
                    mma16816(acc[mt][nt], ah[mt][0], ah[mt][1], ah[mt][2], ah[mt][3], bh[nt][0], bh[nt][1]);
                    mma16816(acc[mt][nt], ah[mt][0], ah[mt][1], ah[mt][2], ah[mt][3], bl[nt][0], bl[nt][1]);
                    mma16816(acc[mt][nt], al[mt][0], al[mt][1], al[mt][2], al[mt][3], bh[nt][0], bh[nt][1]);
                }
            }
        }
    }
    float* t5b = g_t5 + n * 16384;
    int r0 = lane >> 2, c0 = 2 * (lane & 3);
    #pragma unroll
    for (int mt = 0; mt < 4; mt++) {
        #pragma unroll
        for (int nt = 0; nt < 4; nt++) {
            int row = wm * 64 + mt * 16 + r0, col = wn * 32 + nt * 8 + c0;
            atomicAdd(&t5b[row * 128 + col],           acc[mt][nt][0]);
            atomicAdd(&t5b[row * 128 + col + 1],       acc[mt][nt][1]);
            atomicAdd(&t5b[(row + 8) * 128 + col],     acc[mt][nt][2]);
            atomicAdd(&t5b[(row + 8) * 128 + col + 1], acc[mt][nt][3]);
        }
    }
}

// ---------------------------------------------------------------------------
// K4: prep2
// ---------------------------------------------------------------------------
__global__ void k_prep2(const float* __restrict__ w9) {
    int i = blockIdx.x * 256 + threadIdx.x;
    if (i >= Nn * 16384) return;
    int c = i & 127, d = (i >> 7) & 127, n = i >> 14;
    const float SCALE = 1.0f / (112.0f * 11.313708498984761f);
    float v = g_t5[n * 16384 + c * 128 + d] * w9[c * 128 + d] * SCALE;
    __nv_bfloat16 hh, ll;
    bsplit(v, hh, ll);
    g_amh[i] = hh;
    g_aml[i] = ll;
}

// ---------------------------------------------------------------------------
// K7: t14 via bf16x3 mma; ACCUMULATES into out
// ---------------------------------------------------------------------------
__global__ void __launch_bounds__(256, 2) k_t14(float* __restrict__ out) {
    extern __shared__ __nv_bfloat16 sm4[];
    __nv_bfloat16* sAh = sm4;                   // [128][136]
    __nv_bfloat16* sAl = sm4 + 128 * 136;
    __nv_bfloat16* sBh = sm4 + 2 * 128 * 136;   // [32][136]
    __nv_bfloat16* sBl = sBh + 32 * 136;
    int n = blockIdx.y, tid = threadIdx.x, lane = tid & 31, warp = tid >> 5;
    int wm = warp >> 2, wn = warp & 3;
    int s0 = blockIdx.x * 448;

    for (int i = tid; i < 128 * 16; i += 256) {
        int r = i >> 4, q = i & 15;
        *reinterpret_cast<uint4*>(sAh + r * 136 + q * 8) =
            *reinterpret_cast<const uint4*>(g_amh + n * 16384 + i * 8);
        *reinterpret_cast<uint4*>(sAl + r * 136 + q * 8) =
            *reinterpret_cast<const uint4*>(g_aml + n * 16384 + i * 8);
    }

    int qa_row = (lane & 7) + ((lane >> 3) & 1) * 8;
    int qa_col = (lane >> 4) * 8;
    int lb = lane & 15;
    int qb_row = lb & 7, qb_col = (lb >> 3) * 8;
    u32 aH = smem_u32(sAh), aL = smem_u32(sAl), bH = smem_u32(sBh), bL = smem_u32(sBl);
    int r0 = lane >> 2, c0 = 2 * (lane & 3);
    float* ob = out + (size_t)n * CHW;

    for (int st = 0; st < 14; st++) {
        __syncthreads();
        for (int i = tid; i < 32 * 16; i += 256) {
            int r = i >> 4, q = i & 15;
            int s = s0 + st * 32 + r;
            int h = s / 112, w = s - h * 112;
            size_t off = ((size_t)(n * Hh + h) * T2T_ROW + (w + 2)) * 128 + q * 8;
            *reinterpret_cast<uint4*>(sBh + r * 136 + q * 8) =
                *reinterpret_cast<const uint4*>(g_t2Th + off);
            *reinterpret_cast<uint4*>(sBl + r * 136 + q * 8) =
                *reinterpret_cast<const uint4*>(g_t2Tl + off);
        }
        __syncthreads();

        float acc[4][4];
        #pragma unroll
        for (int a = 0; a < 4; a++)
            #pragma unroll
            for (int c = 0; c < 4; c++) acc[a][c] = 0.f;

        #pragma unroll
        for (int k0 = 0; k0 < 128; k0 += 16) {
            u32 ah[4][4], al[4][4], bh[2], bl[2];
            #pragma unroll
            for (int mt = 0; mt < 4; mt++) {
                u32 off = (u32)(((wm * 64 + mt * 16 + qa_row) * 136 + k0 + qa_col) * 2);
                ldsm4(ah[mt][0], ah[mt][1], ah[mt][2], ah[mt][3], aH + off);
                ldsm4(al[mt][0], al[mt][1], al[mt][2], al[mt][3], aL + off);
            }
            {
                u32 off = (u32)(((wn * 8 + qb_row) * 136 + k0 + qb_col) * 2);
                ldsm2(bh[0], bh[1], bH + off);
                ldsm2(bl[0], bl[1], bL + off);
            }
            #pragma unroll
            for (int mt = 0; mt < 4; mt++) {
                mma16816(acc[mt], ah[mt][0], ah[mt][1], ah[mt][2], ah[mt][3], bh[0], bh[1]);
                mma16816(acc[mt], ah[mt][0], ah[mt][1], ah[mt][2], ah[mt][3], bl[0], bl[1]);
                mma16816(acc[mt], al[mt][0], al[mt][1], al[mt][2], al[mt][3], bh[0], bh[1]);
            }
        }
        #pragma unroll
        for (int mt = 0; mt < 4; mt++) {
            int row = wm * 64 + mt * 16 + r0;
            int s = s0 + st * 32 + wn * 8 + c0;
            ob[(size_t)row * HW + s]           += acc[mt][0];
            ob[(size_t)row * HW + s + 1]       += acc[mt][1];
            ob[(size_t)(row + 8) * HW + s]     += acc[mt][2];
            ob[(size_t)(row + 8) * HW + s + 1] += acc[mt][3];
        }
    }
}

// ---------------------------------------------------------------------------
// K5: conv3 via 1-pass bf16 mma
// ---------------------------------------------------------------------------
__global__ void __launch_bounds__(256, 2) k_conv3() {
    extern __shared__ __nv_bfloat16 sm3[];
    __nv_bfloat16* sBh = sm3;                   // [132][136]
    __nv_bfloat16* sAh = sm3 + 132 * 136;       // [128][136]
    int h = blockIdx.x, n = blockIdx.y, tid = threadIdx.x, lane = tid & 31, warp = tid >> 5;
    int wm = warp >> 2, wn = warp & 3;

    size_t tb = ((size_t)(n * Hh + h)) * T2T_H;
    for (int i = tid; i < 132 * 16; i += 256) {
        int wp = i >> 4, q = i & 15;
        uint4 vh = make_uint4(0, 0, 0, 0);
        if (wp < 116)
            vh = *reinterpret_cast<const uint4*>(g_t2Th + tb + wp * 128 + q * 8);
        *reinterpret_cast<uint4*>(sBh + wp * 136 + q * 8) = vh;
    }

    float acc[4][4][4];
    #pragma unroll
    for (int a = 0; a < 4; a++)
        #pragma unroll
        for (int b = 0; b < 4; b++)
            #pragma unroll
            for (int c = 0; c < 4; c++) acc[a][b][c] = 0.f;

    int qa_row = (lane & 7) + ((lane >> 3) & 1) * 8;
    int qa_col = (lane >> 4) * 8;
    int lb = lane & 15;
    int qb_row = lb & 7, qb_col = (lb >> 3) * 8;
    u32 aH = smem_u32(sAh), bH = smem_u32(sBh);

    for (int kk = 0; kk < 3; kk++) {
        __syncthreads();
        for (int i = tid; i < 128 * 16; i += 256) {
            int o = i >> 4, q = i & 15;
            *reinterpret_cast<uint4*>(sAh + o * 136 + q * 8) =
                *reinterpret_cast<const uint4*>(g_w3h + kk * 16384 + o * 128 + q * 8);
        }
        __syncthreads();
        int roff = 2 * kk;
        #pragma unroll
        for (int k0 = 0; k0 < 128; k0 += 16) {
            u32 ah[4][4], bh[4][2];
            #pragma unroll
            for (int mt = 0; mt < 4; mt++) {
                u32 off = (u32)(((wm * 64 + mt * 16 + qa_row) * 136 + k0 + qa_col) * 2);
                ldsm4(ah[mt][0], ah[mt][1], ah[mt][2], ah[mt][3], aH + off);
            }
            #pragma unroll
            for (int nt = 0; nt < 4; nt++) {
                u32 off = (u32)(((wn * 32 + nt * 8 + qb_row + roff) * 136 + k0 + qb_col) * 2);
                ldsm2(bh[nt][0], bh[nt][1], bH + off);
            }
            #pragma unroll
            for (int mt = 0; mt < 4; mt++)
                #pragma unroll
                for (int nt = 0; nt < 4; nt++)
                    mma16816(acc[mt][nt], ah[mt][0], ah[mt][1], ah[mt][2], ah[mt][3], bh[nt][0], bh[nt][1]);
        }
    }
    __syncthreads();
    float* ob = (float*)sm3;   // [128][116]
    int r0 = lane >> 2, c0 = 2 * (lane & 3);
    #pragma unroll
    for (int mt = 0; mt < 4; mt++) {
        #pragma unroll
        for (int nt = 0; nt < 4; nt++) {
            int row = wm * 64 + mt * 16 + r0, col = wn * 32 + nt * 8 + c0;
            if (col < 112) {
                ob[row * 116 + col]           = acc[mt][nt][0];
                ob[row * 116 + col + 1]       = acc[mt][nt][1];
                ob[(row + 8) * 116 + col]     = acc[mt][nt][2];
                ob[(row + 8) * 116 + col + 1] = acc[mt][nt][3];
            }
        }
    }
    __syncthreads();
    float* dst = g_t3 + (size_t)n * CHW + (size_t)h * Ww;
    for (int i = tid; i < 128 * 112; i += 256) {
        int o = i / 112, w = i - o * 112;
        dst[(size_t)o * HW + w] = ob[o * 116 + w];
    }
}

// ---------------------------------------------------------------------------
// K6: t4r = depthwise conv + both t15 rolls + transpose, bf16 [n][h][w'][c]
// ---------------------------------------------------------------------------
__global__ void __launch_bounds__(256) k_t4r(const float* __restrict__ w4) {
    __shared__ __nv_bfloat16 ts[112 * 136];   // [w'][c]
    __shared__ float wks[128 * 7];
    int h = blockIdx.x, n = blockIdx.y, tid = threadIdx.x;
    for (int i = tid; i < 128 * 7; i += 256) wks[i] = w4[i];
    __syncthreads();
    for (int i = tid; i < 128 * 112; i += 256) {
        int cs = i / 112, ws = i - cs * 112;
        const float* base = g_t3 + (size_t)(n * 128 + cs) * HW + ws;
        float acc = 0.f;
        #pragma unroll
        for (int k = 0; k < 7; k++) {
            int hh = h - 9 + 3 * k;
            if (hh >= 0 && hh < Hh) acc += base[(size_t)hh * Ww] * wks[cs * 7 + k];
        }
        int c = (cs + 2) & 127;
        int w = ws + 2; if (w >= 112) w -= 112;
        ts[w * 136 + c] = __float2bfloat16(acc);
    }
    __syncthreads();
    __nv_bfloat16* dst = g_t4r + (size_t)(n * Hh + h) * 14336;
    for (int i = tid; i < 112 * 16; i += 256) {
        int w = i >> 4, q = i & 15;
        *reinterpret_cast<uint4*>(dst + w * 128 + q * 8) =
            *reinterpret_cast<const uint4*>(ts + w * 136 + q * 8);
    }
}

// ---------------------------------------------------------------------------
// K8: t15 via 1-pass bf16 mma, double-buffered B, 512 threads (j split 7/7)
// ---------------------------------------------------------------------------
#define T15_BUF (112 * 136)
__global__ void __launch_bounds__(512, 1) k_t15(float* __restrict__ out) {
    extern __shared__ __nv_bfloat16 smt[];
    __nv_bfloat16* sA = smt;               // [128 o][232]
    __nv_bfloat16* sB = smt + 128 * 232;   // [2][112 w][136]
    int h = blockIdx.x, n = blockIdx.y;
    int tid = threadIdx.x, lane = tid & 31, warp = tid >> 5;   // 16 warps
    int ow = warp & 7;                      // o-row group
    int jh = warp >> 3;                     // j half: 0 -> j 0..6, 1 -> j 7..13
    int g = ow >> 1;                        // channel group
    int h2 = (h + 2) % Hh;

    // valid tap list (uniform across block)
    int kt[7], rr[7], nv = 0;
    for (int k = 0; k < 7; k++) {
        int r = h2 + 2 * k - 6;
        if (r >= 0 && r < Hh) { kt[nv] = k; rr[nv] = r; nv++; }
    }

    // stage A
    for (int i = tid; i < 128 * 28; i += 512) {
        int o = i / 28, q = i % 28;
        *reinterpret_cast<uint4*>(sA + o * 232 + q * 8) =
            *reinterpret_cast<const uint4*>(g_weffb + o * 224 + q * 8);
    }
    // stage first B tile into buffer 0
    {
        const __nv_bfloat16* src = g_t4r + (size_t)(n * Hh + rr[0]) * 14336;
        for (int i = tid; i < 112 * 16; i += 512) {
            int w = i >> 4, q = i & 15;
            *reinterpret_cast<uint4*>(sB + w * 136 + q * 8) =
                *reinterpret_cast<const uint4*>(src + w * 128 + q * 8);
        }
    }
    __syncthreads();

    int qa_row = (lane & 7) + ((lane >> 3) & 1) * 8;
    int qa_col = (lane >> 4) * 8;
    int lb = lane & 15;
    int qb_row = lb & 7, qb_col = (lb >> 3) * 8;
    u32 aP = smem_u32(sA);
    u32 bP0 = smem_u32(sB);

    float acc[7][4];
    #pragma unroll
    for (int j = 0; j < 7; j++)
        #pragma unroll
        for (int c = 0; c < 4; c++) acc[j][c] = 0.f;

    for (int t = 0; t < nv; t++) {
        // prefetch next tap into other buffer (overlaps with mma below)
        if (t + 1 < nv) {
            __nv_bfloat16* dstb = sB + ((t + 1) & 1) * T15_BUF;
            const __nv_bfloat16* src = g_t4r + (size_t)(n * Hh + rr[t + 1]) * 14336;
            for (int i = tid; i < 112 * 16; i += 512) {
                int w = i >> 4, q = i & 15;
                *reinterpret_cast<uint4*>(dstb + w * 136 + q * 8) =
                    *reinterpret_cast<const uint4*>(src + w * 128 + q * 8);
            }
        }
        u32 bP = bP0 + (u32)((t & 1) * T15_BUF * 2);
        int k = kt[t];
        #pragma unroll
        for (int chunk = 0; chunk < 2; chunk++) {
            u32 a0, a1, a2, a3;
            u32 aoff = (u32)(((ow * 16 + qa_row) * 232 + k * 32 + chunk * 16 + qa_col) * 2);
            ldsm4(a0, a1, a2, a3, aP + aoff);
            int bcol = g * 32 + chunk * 16;
            #pragma unroll
            for (int j = 0; j < 7; j++) {
                int jj = jh * 7 + j;
                u32 b0, b1;
                u32 boff = (u32)(((jj * 8 + qb_row) * 136 + bcol + qb_col) * 2);
                ldsm2(b0, b1, bP + boff);
                mma16816(acc[j], a0, a1, a2, a3, b0, b1);
            }
        }
        __syncthreads();
    }
    int r0 = lane >> 2, c0 = 2 * (lane & 3);
    float* ob = out + (size_t)n * CHW + (size_t)h * Ww;
    #pragma unroll
    for (int j = 0; j < 7; j++) {
        int o = ow * 16 + r0;
        int w = (jh * 7 + j) * 8 + c0;
        ob[(size_t)o * HW + w]           = acc[j][0];
        ob[(size_t)o * HW + w + 1]       = acc[j][1];
        ob[(size_t)(o + 8) * HW + w]     = acc[j][2];
        ob[(size_t)(o + 8) * HW + w + 1] = acc[j][3];
    }
}

// ---------------------------------------------------------------------------
extern "C" void kernel_launch(void* const* d_in, const int* in_sizes, int n_in,
                              void* d_out, int out_size) {
    const float* x   = (const float*)d_in[0];
    const float* w3  = (const float*)d_in[1];
    const float* w4  = (const float*)d_in[2];
    const float* w9  = (const float*)d_in[3];
    const float* w10 = (const float*)d_in[4];
    const float* w15 = (const float*)d_in[5];
    float* out = (float*)d_out;

    const int SMEM_SILU = 116 * 129 * 4;                      // 59856
    const int SMEM_T5   = 4 * 128 * 72 * 2;                   // 73728
    const int SMEM_C3   = (132 * 136 + 128 * 136) * 2;        // 70720
    const int SMEM_T14  = (2 * 128 * 136 + 2 * 32 * 136) * 2; // 87040
    const int SMEM_T15  = (128 * 232 + 2 * 112 * 136) * 2;    // 120320
    cudaFuncSetAttribute(k_silu_t, cudaFuncAttributeMaxDynamicSharedMemorySize, SMEM_SILU);
    cudaFuncSetAttribute(k_t5,     cudaFuncAttributeMaxDynamicSharedMemorySize, SMEM_T5);
    cudaFuncSetAttribute(k_conv3,  cudaFuncAttributeMaxDynamicSharedMemorySize, SMEM_C3);
    cudaFuncSetAttribute(k_t14,    cudaFuncAttributeMaxDynamicSharedMemorySize, SMEM_T14);
    cudaFuncSetAttribute(k_t15,    cudaFuncAttributeMaxDynamicSharedMemorySize, SMEM_T15);

    // t15 (writes out) at profiled launch index 3; t14 accumulates after.
    k_silu_t<<< dim3(112, 8), 256, SMEM_SILU >>>(x, w3, w10, w15);  // + embedded prep
    k_conv3 <<< dim3(112, 8), 256, SMEM_C3 >>>();
    k_t4r   <<< dim3(112, 8), 256 >>>(w4);
    k_t15   <<< dim3(112, 8), 512, SMEM_T15 >>>(out);
    k_t5    <<< dim3(28, 8), 256, SMEM_T5 >>>(x);
    k_prep2 <<< 512, 256 >>>(w9);
    k_t14   <<< dim3(28, 8), 256, SMEM_T14 >>>(out);
}

// round 16
// speedup vs baseline: 1.0420x; 1.0420x over previous
#include <cuda_runtime.h>
#include <cuda_bf16.h>
#include <cstdint>
#include <cstddef>
#include <math.h>

typedef unsigned int u32;

#define Nn 8
#define Cc 128
#define Hh 112
#define Ww 112
#define HW (Hh*Ww)          /* 12544 */
#define CHW (Cc*HW)         /* 1605632 */
#define NTOT (Nn*CHW)       /* 12845056 */
#define T2T_ROW 116
#define T2T_H (T2T_ROW*Cc)  /* 14848 per (n,h) */

// ---- global scratch ----
__device__ float g_t3[NTOT];
__device__ __nv_bfloat16 g_t4r[NTOT];                  // t4 rolled+transposed [n][h][w'][c]
__device__ float g_t5[Nn*Cc*Cc];
__device__ __nv_bfloat16 g_t2Th[(size_t)Nn*Hh*T2T_H];  // silu transposed [n][h][w'][c] hi
__device__ __nv_bfloat16 g_t2Tl[(size_t)Nn*Hh*T2T_H];  // lo
__device__ __nv_bfloat16 g_sgh[NTOT];                  // sigmoid(x) [n][c][s] hi
__device__ __nv_bfloat16 g_sgl[NTOT];                  // lo
__device__ __nv_bfloat16 g_w3h[3*Cc*Cc];               // [kk][o][i]
__device__ __nv_bfloat16 g_weffb[Cc*224];              // t15 fused W [o][k*32+cc]
__device__ __nv_bfloat16 g_amh[Nn*Cc*Cc];              // t14 A [n][d][c] hi
__device__ __nv_bfloat16 g_aml[Nn*Cc*Cc];

// ---- helpers ----
__device__ __forceinline__ u32 smem_u32(const void* p) {
    return (u32)__cvta_generic_to_shared(p);
}
__device__ __forceinline__ void ldsm4(u32& r0, u32& r1, u32& r2, u32& r3, u32 a) {
    asm volatile("ldmatrix.sync.aligned.m8n8.x4.shared.b16 {%0,%1,%2,%3},[%4];\n"
                 : "=r"(r0), "=r"(r1), "=r"(r2), "=r"(r3) : "r"(a));
}
__device__ __forceinline__ void ldsm2(u32& r0, u32& r1, u32 a) {
    asm volatile("ldmatrix.sync.aligned.m8n8.x2.shared.b16 {%0,%1},[%2];\n"
                 : "=r"(r0), "=r"(r1) : "r"(a));
}
__device__ __forceinline__ void mma16816(float* c, u32 a0, u32 a1, u32 a2, u32 a3,
                                         u32 b0, u32 b1) {
    asm volatile("mma.sync.aligned.m16n8k16.row.col.f32.bf16.bf16.f32 "
                 "{%0,%1,%2,%3},{%4,%5,%6,%7},{%8,%9},{%0,%1,%2,%3};\n"
                 : "+f"(c[0]), "+f"(c[1]), "+f"(c[2]), "+f"(c[3])
                 : "r"(a0), "r"(a1), "r"(a2), "r"(a3), "r"(b0), "r"(b1));
}
__device__ __forceinline__ void bsplit(float v, __nv_bfloat16& hi, __nv_bfloat16& lo) {
    hi = __float2bfloat16(v);
    lo = __float2bfloat16(v - __bfloat162float(hi));
}
__device__ __forceinline__ u32 pk(__nv_bfloat16 a, __nv_bfloat16 b) {
    return (u32)__bfloat16_as_ushort(a) | ((u32)__bfloat16_as_ushort(b) << 16);
}
__device__ __forceinline__ float fast_sigmoid(float u) {
    float t;
    asm("tanh.approx.f32 %0, %1;" : "=f"(t) : "f"(0.5f * u));
    return fmaf(0.5f, t, 0.5f);   // 1 MUFU instead of 2
}

// ---------------------------------------------------------------------------
// K1: silu(x) -> t2T bf16 hi/lo; sigmoid(x) hi/lo [n][c][s]; embedded prep
// sigmoid via tanh.approx (halves MUFU traffic; abs err ~6e-5)
// ---------------------------------------------------------------------------
__global__ void __launch_bounds__(256) k_silu_t(const float* __restrict__ x,
                                                const float* __restrict__ w3,
                                                const float* __restrict__ w10,
                                                const float* __restrict__ w15) {
    extern __shared__ float ys[];   // [116][129]
    int h = blockIdx.x, n = blockIdx.y, tid = threadIdx.x;
    if (h == 0) {
        float* t5b = g_t5 + n * 16384;
        for (int i = tid; i < 16384; i += 256) t5b[i] = 0.f;
    }
    if (h == 1 && n == 0) {
        for (int i = tid; i < 3 * 128 * 128; i += 256) {
            int ii = i & 127, o = (i >> 7) & 127, kk = i >> 14;
            g_w3h[i] = __float2bfloat16(w3[o * 384 + ii * 3 + kk]);
        }
        for (int i = tid; i < 128 * 224; i += 256) {
            int q = i % 224, o = i / 224;
            int k = q >> 5, cc = q & 31;
            int cabs = ((o >> 5) << 5) + cc;
            g_weffb[i] = __float2bfloat16(w15[o * 224 + cc * 7 + k] * w10[cabs * 7 + k]);
        }
    }
    for (int i = tid; i < 4 * 128; i += 256) {
        int r = i >> 7, c = i & 127;
        int wp = (r < 2) ? r : (112 + r);
        ys[wp * 129 + c] = 0.f;
    }
    const float* xr = x + (size_t)n * CHW + (size_t)h * Ww;
    for (int i = tid; i < 128 * 28; i += 256) {
        int c = i / 28, wq = i % 28;
        float4 v = *reinterpret_cast<const float4*>(xr + (size_t)c * HW + 4 * wq);
        float u[4] = {v.x, v.y, v.z, v.w};
        __nv_bfloat16 sh[4], sl[4];
        #pragma unroll
        for (int j = 0; j < 4; j++) {
            float s = fast_sigmoid(u[j]);
            bsplit(s, sh[j], sl[j]);
            ys[(4 * wq + j + 2) * 129 + c] = u[j] * s;
        }
        size_t so = (size_t)n * CHW + (size_t)c * HW + (size_t)h * Ww + 4 * wq;
        *reinterpret_cast<uint2*>(g_sgh + so) = make_uint2(pk(sh[0], sh[1]), pk(sh[2], sh[3]));
        *reinterpret_cast<uint2*>(g_sgl + so) = make_uint2(pk(sl[0], sl[1]), pk(sl[2], sl[3]));
    }
    __syncthreads();
    size_t base = ((size_t)(n * Hh + h)) * T2T_H;
    for (int i = tid; i < T2T_H / 8; i += 256) {
        int wp = i >> 4, c8 = (i & 15) * 8;
        const float* src = ys + wp * 129 + c8;
        u32 hw[4], lw[4];
        #pragma unroll
        for (int j = 0; j < 4; j++) {
            __nv_bfloat16 h0, l0, h1, l1;
            bsplit(src[2 * j], h0, l0);
            bsplit(src[2 * j + 1], h1, l1);
            hw[j] = pk(h0, h1);
            lw[j] = pk(l0, l1);
        }
        *reinterpret_cast<uint4*>(g_t2Th + base + (size_t)i * 8) = make_uint4(hw[0], hw[1], hw[2], hw[3]);
        *reinterpret_cast<uint4*>(g_t2Tl + base + (size_t)i * 8) = make_uint4(lw[0], lw[1], lw[2], lw[3]);
    }
}

// ---------------------------------------------------------------------------
// K3: t5 (bf16x3; A = precomputed sigmoid copy, B = bsplit(x))
// ---------------------------------------------------------------------------
__global__ void __launch_bounds__(256) k_t5(const float* __restrict__ x) {
    extern __shared__ __nv_bfloat16 sm5[];
    __nv_bfloat16* sAh = sm5;
    __nv_bfloat16* sAl = sm5 + 128 * 72;
    __nv_bfloat16* sBh = sm5 + 2 * 128 * 72;
    __nv_bfloat16* sBl = sm5 + 3 * 128 * 72;
    int n = blockIdx.y, tid = threadIdx.x, lane = tid & 31, warp = tid >> 5;
    int wm = warp >> 2, wn = warp & 3;
    int s0 = blockIdx.x * 448;
    const float* xb = x + (size_t)n * CHW;
    const __nv_bfloat16* sgh = g_sgh + (size_t)n * CHW;
    const __nv_bfloat16* sgl = g_sgl + (size_t)n * CHW;

    float acc[4][4][4];
    #pragma unroll
    for (int a = 0; a < 4; a++)
        #pragma unroll
        for (int b = 0; b < 4; b++)
            #pragma unroll
            for (int c = 0; c < 4; c++) acc[a][b][c] = 0.f;

    int qa_row = (lane & 7) + ((lane >> 3) & 1) * 8;
    int qa_col = (lane >> 4) * 8;
    int lb = lane & 15;
    int qb_row = lb & 7, qb_col = (lb >> 3) * 8;
    u32 aH = smem_u32(sAh), aL = smem_u32(sAl), bH = smem_u32(sBh), bL = smem_u32(sBl);

    for (int st = 0; st < 7; st++) {
        int sb = s0 + st * 64;
        __syncthreads();
        for (int i = tid; i < 128 * 8; i += 256) {
            int c = i >> 3, q = i & 7;
            *reinterpret_cast<uint4*>(sAh + c * 72 + q * 8) =
                *reinterpret_cast<const uint4*>(sgh + (size_t)c * HW + sb + q * 8);
            *reinterpret_cast<uint4*>(sAl + c * 72 + q * 8) =
                *reinterpret_cast<const uint4*>(sgl + (size_t)c * HW + sb + q * 8);
        }
        for (int i = tid; i < 128 * 16; i += 256) {
            int c = i >> 4, q = i & 15;
            float4 v = *reinterpret_cast<const float4*>(xb + (size_t)c * HW + sb + 4 * q);
            float u[4] = {v.x, v.y, v.z, v.w};
            __nv_bfloat16 bh0, bl0, bh1, bl1;
            int idx = c * 72 + 4 * q;
            bsplit(u[0], bh0, bl0); bsplit(u[1], bh1, bl1);
            u32 b01 = pk(bh0, bh1), b01l = pk(bl0, bl1);
            bsplit(u[2], bh0, bl0); bsplit(u[3], bh1, bl1);
            *reinterpret_cast<uint2*>(sBh + idx) = make_uint2(b01, pk(bh0, bh1));
            *reinterpret_cast<uint2*>(sBl + idx) = make_uint2(b01l, pk(bl0, bl1));
        }
        __syncthreads();
        #pragma unroll
        for (int k0 = 0; k0 < 64; k0 += 16) {
            u32 ah[4][4], al[4][4], bh[4][2], bl[4][2];
            #pragma unroll
            for (int mt = 0; mt < 4; mt++) {
                u32 off = (u32)(((wm * 64 + mt * 16 + qa_row) * 72 + k0 + qa_col) * 2);
                ldsm4(ah[mt][0], ah[mt][1], ah[mt][2], ah[mt][3], aH + off);
                ldsm4(al[mt][0], al[mt][1], al[mt][2], al[mt][3], aL + off);
            }
            #pragma unroll
            for (int nt = 0; nt < 4; nt++) {
                u32 off = (u32)(((wn * 32 + nt * 8 + qb_row) * 72 + k0 + qb_col) * 2);
                ldsm2(bh[nt][0], bh[nt][1], bH + off);
                ldsm2(bl[nt][0], bl[nt][1], bL + off);
            }
            #pragma unroll
            for (int mt = 0; mt < 4; mt++) {
                #pragma unroll
                for (int nt = 0; nt < 4; nt++) {
                    mma16816(acc[mt][nt], ah[mt][0], ah[mt][1], ah[mt][2], ah[mt][3], bh[nt][0], bh[nt][1]);
                    mma16816(acc[mt][nt], ah[mt][0], ah[mt][1], ah[mt][2], ah[mt][3], bl[nt][0], bl[nt][1]);
                    mma16816(acc[mt][nt], al[mt][0], al[mt][1], al[mt][2], al[mt][3], bh[nt][0], bh[nt][1]);
                }
            }
        }
    }
    float* t5b = g_t5 + n * 16384;
    int r0 = lane >> 2, c0 = 2 * (lane & 3);
    #pragma unroll
    for (int mt = 0; mt < 4; mt++) {
        #pragma unroll
        for (int nt = 0; nt < 4; nt++) {
            int row = wm * 64 + mt * 16 + r0, col = wn * 32 + nt * 8 + c0;
            atomicAdd(&t5b[row * 128 + col],           acc[mt][nt][0]);
            atomicAdd(&t5b[row * 128 + col + 1],       acc[mt][nt][1]);
            atomicAdd(&t5b[(row + 8) * 128 + col],     acc[mt][nt][2]);
            atomicAdd(&t5b[(row + 8) * 128 + col + 1], acc[mt][nt][3]);
        }
    }
}

// ---------------------------------------------------------------------------
// K4: prep2
// ---------------------------------------------------------------------------
__global__ void k_prep2(const float* __restrict__ w9) {
    int i = blockIdx.x * 256 + threadIdx.x;
    if (i >= Nn * 16384) return;
    int c = i & 127, d = (i >> 7) & 127, n = i >> 14;
    const float SCALE = 1.0f / (112.0f * 11.313708498984761f);
    float v = g_t5[n * 16384 + c * 128 + d] * w9[c * 128 + d] * SCALE;
    __nv_bfloat16 hh, ll;
    bsplit(v, hh, ll);
    g_amh[i] = hh;
    g_aml[i] = ll;
}

// ---------------------------------------------------------------------------
// K7: t14 via bf16x3 mma; ACCUMULATES into out
// ---------------------------------------------------------------------------
__global__ void __launch_bounds__(256, 2) k_t14(float* __restrict__ out) {
    extern __shared__ __nv_bfloat16 sm4[];
    __nv_bfloat16* sAh = sm4;                   // [128][136]
    __nv_bfloat16* sAl = sm4 + 128 * 136;
    __nv_bfloat16* sBh = sm4 + 2 * 128 * 136;   // [32][136]
    __nv_bfloat16* sBl = sBh + 32 * 136;
    int n = blockIdx.y, tid = threadIdx.x, lane = tid & 31, warp = tid >> 5;
    int wm = warp >> 2, wn = warp & 3;
    int s0 = blockIdx.x * 448;

    for (int i = tid; i < 128 * 16; i += 256) {
        int r = i >> 4, q = i & 15;
        *reinterpret_cast<uint4*>(sAh + r * 136 + q * 8) =
            *reinterpret_cast<const uint4*>(g_amh + n * 16384 + i * 8);
        *reinterpret_cast<uint4*>(sAl + r * 136 + q * 8) =
            *reinterpret_cast<const uint4*>(g_aml + n * 16384 + i * 8);
    }

    int qa_row = (lane & 7) + ((lane >> 3) & 1) * 8;
    int qa_col = (lane >> 4) * 8;
    int lb = lane & 15;
    int qb_row = lb & 7, qb_col = (lb >> 3) * 8;
    u32 aH = smem_u32(sAh), aL = smem_u32(sAl), bH = smem_u32(sBh), bL = smem_u32(sBl);
    int r0 = lane >> 2, c0 = 2 * (lane & 3);
    float* ob = out + (size_t)n * CHW;

    for (int st = 0; st < 14; st++) {
        __syncthreads();
        for (int i = tid; i < 32 * 16; i += 256) {
            int r = i >> 4, q = i & 15;
            int s = s0 + st * 32 + r;
            int h = s / 112, w = s - h * 112;
            size_t off = ((size_t)(n * Hh + h) * T2T_ROW + (w + 2)) * 128 + q * 8;
            *reinterpret_cast<uint4*>(sBh + r * 136 + q * 8) =
                *reinterpret_cast<const uint4*>(g_t2Th + off);
            *reinterpret_cast<uint4*>(sBl + r * 136 + q * 8) =
                *reinterpret_cast<const uint4*>(g_t2Tl + off);
        }
        __syncthreads();

        float acc[4][4];
        #pragma unroll
        for (int a = 0; a < 4; a++)
            #pragma unroll
            for (int c = 0; c < 4; c++) acc[a][c] = 0.f;

        #pragma unroll
        for (int k0 = 0; k0 < 128; k0 += 16) {
            u32 ah[4][4], al[4][4], bh[2], bl[2];
            #pragma unroll
            for (int mt = 0; mt < 4; mt++) {
                u32 off = (u32)(((wm * 64 + mt * 16 + qa_row) * 136 + k0 + qa_col) * 2);
                ldsm4(ah[mt][0], ah[mt][1], ah[mt][2], ah[mt][3], aH + off);
                ldsm4(al[mt][0], al[mt][1], al[mt][2], al[mt][3], aL + off);
            }
            {
                u32 off = (u32)(((wn * 8 + qb_row) * 136 + k0 + qb_col) * 2);
                ldsm2(bh[0], bh[1], bH + off);
                ldsm2(bl[0], bl[1], bL + off);
            }
            #pragma unroll
            for (int mt = 0; mt < 4; mt++) {
                mma16816(acc[mt], ah[mt][0], ah[mt][1], ah[mt][2], ah[mt][3], bh[0], bh[1]);
                mma16816(acc[mt], ah[mt][0], ah[mt][1], ah[mt][2], ah[mt][3], bl[0], bl[1]);
                mma16816(acc[mt], al[mt][0], al[mt][1], al[mt][2], al[mt][3], bh[0], bh[1]);
            }
        }
        #pragma unroll
        for (int mt = 0; mt < 4; mt++) {
            int row = wm * 64 + mt * 16 + r0;
            int s = s0 + st * 32 + wn * 8 + c0;
            ob[(size_t)row * HW + s]           += acc[mt][0];
            ob[(size_t)row * HW + s + 1]       += acc[mt][1];
            ob[(size_t)(row + 8) * HW + s]     += acc[mt][2];
            ob[(size_t)(row + 8) * HW + s + 1] += acc[mt][3];
        }
    }
}

// ---------------------------------------------------------------------------
// K5: conv3 via 1-pass bf16 mma
// ---------------------------------------------------------------------------
__global__ void __launch_bounds__(256, 2) k_conv3() {
    extern __shared__ __nv_bfloat16 sm3[];
    __nv_bfloat16* sBh = sm3;                   // [132][136]
    __nv_bfloat16* sAh = sm3 + 132 * 136;       // [128][136]
    int h = blockIdx.x, n = blockIdx.y, tid = threadIdx.x, lane = tid & 31, warp = tid >> 5;
    int wm = warp >> 2, wn = warp & 3;

    size_t tb = ((size_t)(n * Hh + h)) * T2T_H;
    for (int i = tid; i < 132 * 16; i += 256) {
        int wp = i >> 4, q = i & 15;
        uint4 vh = make_uint4(0, 0, 0, 0);
        if (wp < 116)
            vh = *reinterpret_cast<const uint4*>(g_t2Th + tb + wp * 128 + q * 8);
        *reinterpret_cast<uint4*>(sBh + wp * 136 + q * 8) = vh;
    }

    float acc[4][4][4];
    #pragma unroll
    for (int a = 0; a < 4; a++)
        #pragma unroll
        for (int b = 0; b < 4; b++)
            #pragma unroll
            for (int c = 0; c < 4; c++) acc[a][b][c] = 0.f;

    int qa_row = (lane & 7) + ((lane >> 3) & 1) * 8;
    int qa_col = (lane >> 4) * 8;
    int lb = lane & 15;
    int qb_row = lb & 7, qb_col = (lb >> 3) * 8;
    u32 aH = smem_u32(sAh), bH = smem_u32(sBh);

    for (int kk = 0; kk < 3; kk++) {
        __syncthreads();
        for (int i = tid; i < 128 * 16; i += 256) {
            int o = i >> 4, q = i & 15;
            *reinterpret_cast<uint4*>(sAh + o * 136 + q * 8) =
                *reinterpret_cast<const uint4*>(g_w3h + kk * 16384 + o * 128 + q * 8);
        }
        __syncthreads();
        int roff = 2 * kk;
        #pragma unroll
        for (int k0 = 0; k0 < 128; k0 += 16) {
            u32 ah[4][4], bh[4][2];
            #pragma unroll
            for (int mt = 0; mt < 4; mt++) {
                u32 off = (u32)(((wm * 64 + mt * 16 + qa_row) * 136 + k0 + qa_col) * 2);
                ldsm4(ah[mt][0], ah[mt][1], ah[mt][2], ah[mt][3], aH + off);
            }
            #pragma unroll
            for (int nt = 0; nt < 4; nt++) {
                u32 off = (u32)(((wn * 32 + nt * 8 + qb_row + roff) * 136 + k0 + qb_col) * 2);
                ldsm2(bh[nt][0], bh[nt][1], bH + off);
            }
            #pragma unroll
            for (int mt = 0; mt < 4; mt++)
                #pragma unroll
                for (int nt = 0; nt < 4; nt++)
                    mma16816(acc[mt][nt], ah[mt][0], ah[mt][1], ah[mt][2], ah[mt][3], bh[nt][0], bh[nt][1]);
        }
    }
    __syncthreads();
    float* ob = (float*)sm3;   // [128][116]
    int r0 = lane >> 2, c0 = 2 * (lane & 3);
    #pragma unroll
    for (int mt = 0; mt < 4; mt++) {
        #pragma unroll
        for (int nt = 0; nt < 4; nt++) {
            int row = wm * 64 + mt * 16 + r0, col = wn * 32 + nt * 8 + c0;
            if (col < 112) {
                ob[row * 116 + col]           = acc[mt][nt][0];
                ob[row * 116 + col + 1]       = acc[mt][nt][1];
                ob[(row + 8) * 116 + col]     = acc[mt][nt][2];
                ob[(row + 8) * 116 + col + 1] = acc[mt][nt][3];
            }
        }
    }
    __syncthreads();
    float* dst = g_t3 + (size_t)n * CHW + (size_t)h * Ww;
    for (int i = tid; i < 128 * 112; i += 256) {
        int o = i / 112, w = i - o * 112;
        dst[(size_t)o * HW + w] = ob[o * 116 + w];
    }
}

// ---------------------------------------------------------------------------
// K6: t4r = depthwise conv + both t15 rolls + transpose, bf16 [n][h][w'][c]
// ---------------------------------------------------------------------------
__global__ void __launch_bounds__(256) k_t4r(const float* __restrict__ w4) {
    __shared__ __nv_bfloat16 ts[112 * 136];   // [w'][c]
    __shared__ float wks[128 * 7];
    int h = blockIdx.x, n = blockIdx.y, tid = threadIdx.x;
    for (int i = tid; i < 128 * 7; i += 256) wks[i] = w4[i];
    __syncthreads();
    for (int i = tid; i < 128 * 112; i += 256) {
        int cs = i / 112, ws = i - cs * 112;
        const float* base = g_t3 + (size_t)(n * 128 + cs) * HW + ws;
        float acc = 0.f;
        #pragma unroll
        for (int k = 0; k < 7; k++) {
            int hh = h - 9 + 3 * k;
            if (hh >= 0 && hh < Hh) acc += base[(size_t)hh * Ww] * wks[cs * 7 + k];
        }
        int c = (cs + 2) & 127;
        int w = ws + 2; if (w >= 112) w -= 112;
        ts[w * 136 + c] = __float2bfloat16(acc);
    }
    __syncthreads();
    __nv_bfloat16* dst = g_t4r + (size_t)(n * Hh + h) * 14336;
    for (int i = tid; i < 112 * 16; i += 256) {
        int w = i >> 4, q = i & 15;
        *reinterpret_cast<uint4*>(dst + w * 128 + q * 8) =
            *reinterpret_cast<const uint4*>(ts + w * 136 + q * 8);
    }
}

// ---------------------------------------------------------------------------
// K8: t15 via 1-pass bf16 mma; staging = pure uint4 copy (R14 version, 256 thr)
// ---------------------------------------------------------------------------
__global__ void __launch_bounds__(256, 2) k_t15(float* __restrict__ out) {
    extern __shared__ __nv_bfloat16 smt[];
    __nv_bfloat16* sA = smt;               // [128 o][232]
    __nv_bfloat16* sB = smt + 128 * 232;   // [112 w][136]
    int h = blockIdx.x, n = blockIdx.y;
    int tid = threadIdx.x, lane = tid & 31, warp = tid >> 5;
    int g = warp >> 1;
    int h2 = (h + 2) % Hh;

    for (int i = tid; i < 128 * 28; i += 256) {
        int o = i / 28, q = i % 28;
        *reinterpret_cast<uint4*>(sA + o * 232 + q * 8) =
            *reinterpret_cast<const uint4*>(g_weffb + o * 224 + q * 8);
    }

    int qa_row = (lane & 7) + ((lane >> 3) & 1) * 8;
    int qa_col = (lane >> 4) * 8;
    int lb = lane & 15;
    int qb_row = lb & 7, qb_col = (lb >> 3) * 8;
    u32 aP = smem_u32(sA), bP = smem_u32(sB);

    float acc[14][4];
    #pragma unroll
    for (int j = 0; j < 14; j++)
        #pragma unroll
        for (int c = 0; c < 4; c++) acc[j][c] = 0.f;

    for (int k = 0; k < 7; k++) {
        int r = h2 + 2 * k - 6;
        if (r < 0 || r >= Hh) continue;
        __syncthreads();
        const __nv_bfloat16* src = g_t4r + (size_t)(n * Hh + r) * 14336;
        for (int i = tid; i < 112 * 16; i += 256) {
            int w = i >> 4, q = i & 15;
            *reinterpret_cast<uint4*>(sB + w * 136 + q * 8) =
                *reinterpret_cast<const uint4*>(src + w * 128 + q * 8);
        }
        __syncthreads();
        #pragma unroll
        for (int chunk = 0; chunk < 2; chunk++) {
            u32 a0, a1, a2, a3;
            u32 aoff = (u32)(((warp * 16 + qa_row) * 232 + k * 32 + chunk * 16 + qa_col) * 2);
            ldsm4(a0, a1, a2, a3, aP + aoff);
            int bcol = g * 32 + chunk * 16;
            #pragma unroll
            for (int j = 0; j < 14; j++) {
                u32 b0, b1;
                u32 boff = (u32)(((j * 8 + qb_row) * 136 + bcol + qb_col) * 2);
                ldsm2(b0, b1, bP + boff);
                mma16816(acc[j], a0, a1, a2, a3, b0, b1);
            }
        }
    }
    int r0 = lane >> 2, c0 = 2 * (lane & 3);
    float* ob = out + (size_t)n * CHW + (size_t)h * Ww;
    #pragma unroll
    for (int j = 0; j < 14; j++) {
        int o = warp * 16 + r0;
        int w = j * 8 + c0;
        ob[(size_t)o * HW + w]           = acc[j][0];
        ob[(size_t)o * HW + w + 1]       = acc[j][1];
        ob[(size_t)(o + 8) * HW + w]     = acc[j][2];
        ob[(size_t)(o + 8) * HW + w + 1] = acc[j][3];
    }
}

// ---------------------------------------------------------------------------
extern "C" void kernel_launch(void* const* d_in, const int* in_sizes, int n_in,
                              void* d_out, int out_size) {
    const float* x   = (const float*)d_in[0];
    const float* w3  = (const float*)d_in[1];
    const float* w4  = (const float*)d_in[2];
    const float* w9  = (const float*)d_in[3];
    const float* w10 = (const float*)d_in[4];
    const float* w15 = (const float*)d_in[5];
    float* out = (float*)d_out;

    const int SMEM_SILU = 116 * 129 * 4;                      // 59856
    const int SMEM_T5   = 4 * 128 * 72 * 2;                   // 73728
    const int SMEM_C3   = (132 * 136 + 128 * 136) * 2;        // 70720
    const int SMEM_T14  = (2 * 128 * 136 + 2 * 32 * 136) * 2; // 87040
    const int SMEM_T15  = (128 * 232 + 112 * 136) * 2;        // 89856
    cudaFuncSetAttribute(k_silu_t, cudaFuncAttributeMaxDynamicSharedMemorySize, SMEM_SILU);
    cudaFuncSetAttribute(k_t5,     cudaFuncAttributeMaxDynamicSharedMemorySize, SMEM_T5);
    cudaFuncSetAttribute(k_conv3,  cudaFuncAttributeMaxDynamicSharedMemorySize, SMEM_C3);
    cudaFuncSetAttribute(k_t14,    cudaFuncAttributeMaxDynamicSharedMemorySize, SMEM_T14);
    cudaFuncSetAttribute(k_t15,    cudaFuncAttributeMaxDynamicSharedMemorySize, SMEM_T15);

    // t15 (writes out) at profiled launch index 3; t14 accumulates after.
    k_silu_t<<< dim3(112, 8), 256, SMEM_SILU >>>(x, w3, w10, w15);  // + embedded prep
    k_conv3 <<< dim3(112, 8), 256, SMEM_C3 >>>();
    k_t4r   <<< dim3(112, 8), 256 >>>(w4);
    k_t15   <<< dim3(112, 8), 256, SMEM_T15 >>>(out);
    k_t5    <<< dim3(28, 8), 256, SMEM_T5 >>>(x);
    k_prep2 <<< 512, 256 >>>(w9);
    k_t14   <<< dim3(28, 8), 256, SMEM_T14 >>>(out);
}

// round 17
// speedup vs baseline: 1.0544x; 1.0119x over previous
#include <cuda_runtime.h>
#include <cuda_bf16.h>
#include <cstdint>
#include <cstddef>
#include <math.h>

typedef unsigned int u32;

#define Nn 8
#define Cc 128
#define Hh 112
#define Ww 112
#define HW (Hh*Ww)          /* 12544 */
#define CHW (Cc*HW)         /* 1605632 */
#define NTOT (Nn*CHW)       /* 12845056 */
#define T2T_ROW 116
#define T2T_H (T2T_ROW*Cc)  /* 14848 per (n,h) */

// ---- global scratch ----
__device__ float g_t3[NTOT];
__device__ __nv_bfloat16 g_t4r[NTOT];                  // t4 rolled+transposed [n][h][w'][c]
__device__ float g_t5[Nn*Cc*Cc];
__device__ __nv_bfloat16 g_t2Th[(size_t)Nn*Hh*T2T_H];  // silu transposed [n][h][w'][c] hi
__device__ __nv_bfloat16 g_t2Tl[(size_t)Nn*Hh*T2T_H];  // lo
__device__ __nv_bfloat16 g_sgh[NTOT];                  // sigmoid(x) [n][c][s] hi
__device__ __nv_bfloat16 g_sgl[NTOT];                  // lo
__device__ __nv_bfloat16 g_w3h[3*Cc*Cc];               // [kk][o][i]
__device__ __nv_bfloat16 g_weffb[Cc*224];              // t15 fused W [o][k*32+cc]
__device__ __nv_bfloat16 g_amh[Nn*Cc*Cc];              // t14 A [n][d][c] hi
__device__ __nv_bfloat16 g_aml[Nn*Cc*Cc];

// ---- helpers ----
__device__ __forceinline__ u32 smem_u32(const void* p) {
    return (u32)__cvta_generic_to_shared(p);
}
__device__ __forceinline__ void ldsm4(u32& r0, u32& r1, u32& r2, u32& r3, u32 a) {
    asm volatile("ldmatrix.sync.aligned.m8n8.x4.shared.b16 {%0,%1,%2,%3},[%4];\n"
                 : "=r"(r0), "=r"(r1), "=r"(r2), "=r"(r3) : "r"(a));
}
__device__ __forceinline__ void ldsm2(u32& r0, u32& r1, u32 a) {
    asm volatile("ldmatrix.sync.aligned.m8n8.x2.shared.b16 {%0,%1},[%2];\n"
                 : "=r"(r0), "=r"(r1) : "r"(a));
}
__device__ __forceinline__ void mma16816(float* c, u32 a0, u32 a1, u32 a2, u32 a3,
                                         u32 b0, u32 b1) {
    asm volatile("mma.sync.aligned.m16n8k16.row.col.f32.bf16.bf16.f32 "
                 "{%0,%1,%2,%3},{%4,%5,%6,%7},{%8,%9},{%0,%1,%2,%3};\n"
                 : "+f"(c[0]), "+f"(c[1]), "+f"(c[2]), "+f"(c[3])
                 : "r"(a0), "r"(a1), "r"(a2), "r"(a3), "r"(b0), "r"(b1));
}
__device__ __forceinline__ void bsplit(float v, __nv_bfloat16& hi, __nv_bfloat16& lo) {
    hi = __float2bfloat16(v);
    lo = __float2bfloat16(v - __bfloat162float(hi));
}
__device__ __forceinline__ u32 pk(__nv_bfloat16 a, __nv_bfloat16 b) {
    return (u32)__bfloat16_as_ushort(a) | ((u32)__bfloat16_as_ushort(b) << 16);
}
__device__ __forceinline__ float fast_sigmoid(float u) {
    float t;
    asm("tanh.approx.f32 %0, %1;" : "=f"(t) : "f"(0.5f * u));
    return fmaf(0.5f, t, 0.5f);
}

// ---------------------------------------------------------------------------
// K1: silu(x) -> t2T bf16 hi/lo; sigmoid(x) hi/lo [n][c][s]; embedded prep
// ---------------------------------------------------------------------------
__global__ void __launch_bounds__(256) k_silu_t(const float* __restrict__ x,
                                                const float* __restrict__ w3,
                                                const float* __restrict__ w10,
                                                const float* __restrict__ w15) {
    extern __shared__ float ys[];   // [116][129]
    int h = blockIdx.x, n = blockIdx.y, tid = threadIdx.x;
    if (h == 0) {
        float* t5b = g_t5 + n * 16384;
        for (int i = tid; i < 16384; i += 256) t5b[i] = 0.f;
    }
    if (h == 1 && n == 0) {
        for (int i = tid; i < 3 * 128 * 128; i += 256) {
            int ii = i & 127, o = (i >> 7) & 127, kk = i >> 14;
            g_w3h[i] = __float2bfloat16(w3[o * 384 + ii * 3 + kk]);
        }
        for (int i = tid; i < 128 * 224; i += 256) {
            int q = i % 224, o = i / 224;
            int k = q >> 5, cc = q & 31;
            int cabs = ((o >> 5) << 5) + cc;
            g_weffb[i] = __float2bfloat16(w15[o * 224 + cc * 7 + k] * w10[cabs * 7 + k]);
        }
    }
    for (int i = tid; i < 4 * 128; i += 256) {
        int r = i >> 7, c = i & 127;
        int wp = (r < 2) ? r : (112 + r);
        ys[wp * 129 + c] = 0.f;
    }
    const float* xr = x + (size_t)n * CHW + (size_t)h * Ww;
    for (int i = tid; i < 128 * 28; i += 256) {
        int c = i / 28, wq = i % 28;
        float4 v = *reinterpret_cast<const float4*>(xr + (size_t)c * HW + 4 * wq);
        float u[4] = {v.x, v.y, v.z, v.w};
        __nv_bfloat16 sh[4], sl[4];
        #pragma unroll
        for (int j = 0; j < 4; j++) {
            float s = fast_sigmoid(u[j]);
            bsplit(s, sh[j], sl[j]);
            ys[(4 * wq + j + 2) * 129 + c] = u[j] * s;
        }
        size_t so = (size_t)n * CHW + (size_t)c * HW + (size_t)h * Ww + 4 * wq;
        *reinterpret_cast<uint2*>(g_sgh + so) = make_uint2(pk(sh[0], sh[1]), pk(sh[2], sh[3]));
        *reinterpret_cast<uint2*>(g_sgl + so) = make_uint2(pk(sl[0], sl[1]), pk(sl[2], sl[3]));
    }
    __syncthreads();
    size_t base = ((size_t)(n * Hh + h)) * T2T_H;
    for (int i = tid; i < T2T_H / 8; i += 256) {
        int wp = i >> 4, c8 = (i & 15) * 8;
        const float* src = ys + wp * 129 + c8;
        u32 hw[4], lw[4];
        #pragma unroll
        for (int j = 0; j < 4; j++) {
            __nv_bfloat16 h0, l0, h1, l1;
            bsplit(src[2 * j], h0, l0);
            bsplit(src[2 * j + 1], h1, l1);
            hw[j] = pk(h0, h1);
            lw[j] = pk(l0, l1);
        }
        *reinterpret_cast<uint4*>(g_t2Th + base + (size_t)i * 8) = make_uint4(hw[0], hw[1], hw[2], hw[3]);
        *reinterpret_cast<uint4*>(g_t2Tl + base + (size_t)i * 8) = make_uint4(lw[0], lw[1], lw[2], lw[3]);
    }
}

// ---------------------------------------------------------------------------
// K3: t5 (bf16x3); B loads via ldsm4 nt-pairs
// ---------------------------------------------------------------------------
__global__ void __launch_bounds__(256) k_t5(const float* __restrict__ x) {
    extern __shared__ __nv_bfloat16 sm5[];
    __nv_bfloat16* sAh = sm5;
    __nv_bfloat16* sAl = sm5 + 128 * 72;
    __nv_bfloat16* sBh = sm5 + 2 * 128 * 72;
    __nv_bfloat16* sBl = sm5 + 3 * 128 * 72;
    int n = blockIdx.y, tid = threadIdx.x, lane = tid & 31, warp = tid >> 5;
    int wm = warp >> 2, wn = warp & 3;
    int s0 = blockIdx.x * 448;
    const float* xb = x + (size_t)n * CHW;
    const __nv_bfloat16* sgh = g_sgh + (size_t)n * CHW;
    const __nv_bfloat16* sgl = g_sgl + (size_t)n * CHW;

    float acc[4][4][4];
    #pragma unroll
    for (int a = 0; a < 4; a++)
        #pragma unroll
        for (int b = 0; b < 4; b++)
            #pragma unroll
            for (int c = 0; c < 4; c++) acc[a][b][c] = 0.f;

    int qa_row = (lane & 7) + ((lane >> 3) & 1) * 8;
    int qa_col = (lane >> 4) * 8;
    int qb4_row = (lane & 7) + ((lane >> 4) & 1) * 8;   // B x4 pair mapping
    int qb4_col = ((lane >> 3) & 1) * 8;
    u32 aH = smem_u32(sAh), aL = smem_u32(sAl), bH = smem_u32(sBh), bL = smem_u32(sBl);

    for (int st = 0; st < 7; st++) {
        int sb = s0 + st * 64;
        __syncthreads();
        for (int i = tid; i < 128 * 8; i += 256) {
            int c = i >> 3, q = i & 7;
            *reinterpret_cast<uint4*>(sAh + c * 72 + q * 8) =
                *reinterpret_cast<const uint4*>(sgh + (size_t)c * HW + sb + q * 8);
            *reinterpret_cast<uint4*>(sAl + c * 72 + q * 8) =
                *reinterpret_cast<const uint4*>(sgl + (size_t)c * HW + sb + q * 8);
        }
        for (int i = tid; i < 128 * 16; i += 256) {
            int c = i >> 4, q = i & 15;
            float4 v = *reinterpret_cast<const float4*>(xb + (size_t)c * HW + sb + 4 * q);
            float u[4] = {v.x, v.y, v.z, v.w};
            __nv_bfloat16 bh0, bl0, bh1, bl1;
            int idx = c * 72 + 4 * q;
            bsplit(u[0], bh0, bl0); bsplit(u[1], bh1, bl1);
            u32 b01 = pk(bh0, bh1), b01l = pk(bl0, bl1);
            bsplit(u[2], bh0, bl0); bsplit(u[3], bh1, bl1);
            *reinterpret_cast<uint2*>(sBh + idx) = make_uint2(b01, pk(bh0, bh1));
            *reinterpret_cast<uint2*>(sBl + idx) = make_uint2(b01l, pk(bl0, bl1));
        }
        __syncthreads();
        #pragma unroll
        for (int k0 = 0; k0 < 64; k0 += 16) {
            u32 ah[4][4], al[4][4], bh[4][2], bl[4][2];
            #pragma unroll
            for (int mt = 0; mt < 4; mt++) {
                u32 off = (u32)(((wm * 64 + mt * 16 + qa_row) * 72 + k0 + qa_col) * 2);
                ldsm4(ah[mt][0], ah[mt][1], ah[mt][2], ah[mt][3], aH + off);
                ldsm4(al[mt][0], al[mt][1], al[mt][2], al[mt][3], aL + off);
            }
            #pragma unroll
            for (int np = 0; np < 2; np++) {
                u32 off = (u32)(((wn * 32 + np * 16 + qb4_row) * 72 + k0 + qb4_col) * 2);
                ldsm4(bh[2*np][0], bh[2*np][1], bh[2*np+1][0], bh[2*np+1][1], bH + off);
                ldsm4(bl[2*np][0], bl[2*np][1], bl[2*np+1][0], bl[2*np+1][1], bL + off);
            }
            #pragma unroll
            for (int mt = 0; mt < 4; mt++) {
                #pragma unroll
                for (int nt = 0; nt < 4; nt++) {
                    mma16816(acc[mt][nt], ah[mt][0], ah[mt][1], ah[mt][2], ah[mt][3], bh[nt][0], bh[nt][1]);
                    mma16816(acc[mt][nt], ah[mt][0], ah[mt][1], ah[mt][2], ah[mt][3], bl[nt][0], bl[nt][1]);
                    mma16816(acc[mt][nt], al[mt][0], al[mt][1], al[mt][2], al[mt][3], bh[nt][0], bh[nt][1]);
                }
            }
        }
    }
    float* t5b = g_t5 + n * 16384;
    int r0 = lane >> 2, c0 = 2 * (lane & 3);
    #pragma unroll
    for (int mt = 0; mt < 4; mt++) {
        #pragma unroll
        for (int nt = 0; nt < 4; nt++) {
            int row = wm * 64 + mt * 16 + r0, col = wn * 32 + nt * 8 + c0;
            atomicAdd(&t5b[row * 128 + col],           acc[mt][nt][0]);
            atomicAdd(&t5b[row * 128 + col + 1],       acc[mt][nt][1]);
            atomicAdd(&t5b[(row + 8) * 128 + col],     acc[mt][nt][2]);
            atomicAdd(&t5b[(row + 8) * 128 + col + 1], acc[mt][nt][3]);
        }
    }
}

// ---------------------------------------------------------------------------
// K4: prep2
// ---------------------------------------------------------------------------
__global__ void k_prep2(const float* __restrict__ w9) {
    int i = blockIdx.x * 256 + threadIdx.x;
    if (i >= Nn * 16384) return;
    int c = i & 127, d = (i >> 7) & 127, n = i >> 14;
    const float SCALE = 1.0f / (112.0f * 11.313708498984761f);
    float v = g_t5[n * 16384 + c * 128 + d] * w9[c * 128 + d] * SCALE;
    __nv_bfloat16 hh, ll;
    bsplit(v, hh, ll);
    g_amh[i] = hh;
    g_aml[i] = ll;
}

// ---------------------------------------------------------------------------
// K7: t14 via bf16x3 mma; ACCUMULATES into out
// ---------------------------------------------------------------------------
__global__ void __launch_bounds__(256, 2) k_t14(float* __restrict__ out) {
    extern __shared__ __nv_bfloat16 sm4[];
    __nv_bfloat16* sAh = sm4;                   // [128][136]
    __nv_bfloat16* sAl = sm4 + 128 * 136;
    __nv_bfloat16* sBh = sm4 + 2 * 128 * 136;   // [32][136]
    __nv_bfloat16* sBl = sBh + 32 * 136;
    int n = blockIdx.y, tid = threadIdx.x, lane = tid & 31, warp = tid >> 5;
    int wm = warp >> 2, wn = warp & 3;
    int s0 = blockIdx.x * 448;

    for (int i = tid; i < 128 * 16; i += 256) {
        int r = i >> 4, q = i & 15;
        *reinterpret_cast<uint4*>(sAh + r * 136 + q * 8) =
            *reinterpret_cast<const uint4*>(g_amh + n * 16384 + i * 8);
        *reinterpret_cast<uint4*>(sAl + r * 136 + q * 8) =
            *reinterpret_cast<const uint4*>(g_aml + n * 16384 + i * 8);
    }

    int qa_row = (lane & 7) + ((lane >> 3) & 1) * 8;
    int qa_col = (lane >> 4) * 8;
    int lb = lane & 15;
    int qb_row = lb & 7, qb_col = (lb >> 3) * 8;
    u32 aH = smem_u32(sAh), aL = smem_u32(sAl), bH = smem_u32(sBh), bL = smem_u32(sBl);
    int r0 = lane >> 2, c0 = 2 * (lane & 3);
    float* ob = out + (size_t)n * CHW;

    for (int st = 0; st < 14; st++) {
        __syncthreads();
        for (int i = tid; i < 32 * 16; i += 256) {
            int r = i >> 4, q = i & 15;
            int s = s0 + st * 32 + r;
            int h = s / 112, w = s - h * 112;
            size_t off = ((size_t)(n * Hh + h) * T2T_ROW + (w + 2)) * 128 + q * 8;
            *reinterpret_cast<uint4*>(sBh + r * 136 + q * 8) =
                *reinterpret_cast<const uint4*>(g_t2Th + off);
            *reinterpret_cast<uint4*>(sBl + r * 136 + q * 8) =
                *reinterpret_cast<const uint4*>(g_t2Tl + off);
        }
        __syncthreads();

        float acc[4][4];
        #pragma unroll
        for (int a = 0; a < 4; a++)
            #pragma unroll
            for (int c = 0; c < 4; c++) acc[a][c] = 0.f;

        #pragma unroll
        for (int k0 = 0; k0 < 128; k0 += 16) {
            u32 ah[4][4], al[4][4], bh[2], bl[2];
            #pragma unroll
            for (int mt = 0; mt < 4; mt++) {
                u32 off = (u32)(((wm * 64 + mt * 16 + qa_row) * 136 + k0 + qa_col) * 2);
                ldsm4(ah[mt][0], ah[mt][1], ah[mt][2], ah[mt][3], aH + off);
                ldsm4(al[mt][0], al[mt][1], al[mt][2], al[mt][3], aL + off);
            }
            {
                u32 off = (u32)(((wn * 8 + qb_row) * 136 + k0 + qb_col) * 2);
                ldsm2(bh[0], bh[1], bH + off);
                ldsm2(bl[0], bl[1], bL + off);
            }
            #pragma unroll
            for (int mt = 0; mt < 4; mt++) {
                mma16816(acc[mt], ah[mt][0], ah[mt][1], ah[mt][2], ah[mt][3], bh[0], bh[1]);
                mma16816(acc[mt], ah[mt][0], ah[mt][1], ah[mt][2], ah[mt][3], bl[0], bl[1]);
                mma16816(acc[mt], al[mt][0], al[mt][1], al[mt][2], al[mt][3], bh[0], bh[1]);
            }
        }
        #pragma unroll
        for (int mt = 0; mt < 4; mt++) {
            int row = wm * 64 + mt * 16 + r0;
            int s = s0 + st * 32 + wn * 8 + c0;
            ob[(size_t)row * HW + s]           += acc[mt][0];
            ob[(size_t)row * HW + s + 1]       += acc[mt][1];
            ob[(size_t)(row + 8) * HW + s]     += acc[mt][2];
            ob[(size_t)(row + 8) * HW + s + 1] += acc[mt][3];
        }
    }
}

// ---------------------------------------------------------------------------
// K5: conv3 via 1-pass bf16 mma
// ---------------------------------------------------------------------------
__global__ void __launch_bounds__(256, 2) k_conv3() {
    extern __shared__ __nv_bfloat16 sm3[];
    __nv_bfloat16* sBh = sm3;                   // [132][136]
    __nv_bfloat16* sAh = sm3 + 132 * 136;       // [128][136]
    int h = blockIdx.x, n = blockIdx.y, tid = threadIdx.x, lane = tid & 31, warp = tid >> 5;
    int wm = warp >> 2, wn = warp & 3;

    size_t tb = ((size_t)(n * Hh + h)) * T2T_H;
    for (int i = tid; i < 132 * 16; i += 256) {
        int wp = i >> 4, q = i & 15;
        uint4 vh = make_uint4(0, 0, 0, 0);
        if (wp < 116)
            vh = *reinterpret_cast<const uint4*>(g_t2Th + tb + wp * 128 + q * 8);
        *reinterpret_cast<uint4*>(sBh + wp * 136 + q * 8) = vh;
    }

    float acc[4][4][4];
    #pragma unroll
    for (int a = 0; a < 4; a++)
        #pragma unroll
        for (int b = 0; b < 4; b++)
            #pragma unroll
            for (int c = 0; c < 4; c++) acc[a][b][c] = 0.f;

    int qa_row = (lane & 7) + ((lane >> 3) & 1) * 8;
    int qa_col = (lane >> 4) * 8;
    int lb = lane & 15;
    int qb_row = lb & 7, qb_col = (lb >> 3) * 8;
    u32 aH = smem_u32(sAh), bH = smem_u32(sBh);

    for (int kk = 0; kk < 3; kk++) {
        __syncthreads();
        for (int i = tid; i < 128 * 16; i += 256) {
            int o = i >> 4, q = i & 15;
            *reinterpret_cast<uint4*>(sAh + o * 136 + q * 8) =
                *reinterpret_cast<const uint4*>(g_w3h + kk * 16384 + o * 128 + q * 8);
        }
        __syncthreads();
        int roff = 2 * kk;
        #pragma unroll
        for (int k0 = 0; k0 < 128; k0 += 16) {
            u32 ah[4][4], bh[4][2];
            #pragma unroll
            for (int mt = 0; mt < 4; mt++) {
                u32 off = (u32)(((wm * 64 + mt * 16 + qa_row) * 136 + k0 + qa_col) * 2);
                ldsm4(ah[mt][0], ah[mt][1], ah[mt][2], ah[mt][3], aH + off);
            }
            #pragma unroll
            for (int nt = 0; nt < 4; nt++) {
                u32 off = (u32)(((wn * 32 + nt * 8 + qb_row + roff) * 136 + k0 + qb_col) * 2);
                ldsm2(bh[nt][0], bh[nt][1], bH + off);
            }
            #pragma unroll
            for (int mt = 0; mt < 4; mt++)
                #pragma unroll
                for (int nt = 0; nt < 4; nt++)
                    mma16816(acc[mt][nt], ah[mt][0], ah[mt][1], ah[mt][2], ah[mt][3], bh[nt][0], bh[nt][1]);
        }
    }
    __syncthreads();
    float* ob = (float*)sm3;   // [128][116]
    int r0 = lane >> 2, c0 = 2 * (lane & 3);
    #pragma unroll
    for (int mt = 0; mt < 4; mt++) {
        #pragma unroll
        for (int nt = 0; nt < 4; nt++) {
            int row = wm * 64 + mt * 16 + r0, col = wn * 32 + nt * 8 + c0;
            if (col < 112) {
                ob[row * 116 + col]           = acc[mt][nt][0];
                ob[row * 116 + col + 1]       = acc[mt][nt][1];
                ob[(row + 8) * 116 + col]     = acc[mt][nt][2];
                ob[(row + 8) * 116 + col + 1] = acc[mt][nt][3];
            }
        }
    }
    __syncthreads();
    float* dst = g_t3 + (size_t)n * CHW + (size_t)h * Ww;
    for (int i = tid; i < 128 * 112; i += 256) {
        int o = i / 112, w = i - o * 112;
        dst[(size_t)o * HW + w] = ob[o * 116 + w];
    }
}

// ---------------------------------------------------------------------------
// K6: t4r = depthwise conv + both t15 rolls + transpose
// ---------------------------------------------------------------------------
__global__ void __launch_bounds__(256) k_t4r(const float* __restrict__ w4) {
    __shared__ __nv_bfloat16 ts[112 * 136];
    __shared__ float wks[128 * 7];
    int h = blockIdx.x, n = blockIdx.y, tid = threadIdx.x;
    for (int i = tid; i < 128 * 7; i += 256) wks[i] = w4[i];
    __syncthreads();
    for (int i = tid; i < 128 * 112; i += 256) {
        int cs = i / 112, ws = i - cs * 112;
        const float* base = g_t3 + (size_t)(n * 128 + cs) * HW + ws;
        float acc = 0.f;
        #pragma unroll
        for (int k = 0; k < 7; k++) {
            int hh = h - 9 + 3 * k;
            if (hh >= 0 && hh < Hh) acc += base[(size_t)hh * Ww] * wks[cs * 7 + k];
        }
        int c = (cs + 2) & 127;
        int w = ws + 2; if (w >= 112) w -= 112;
        ts[w * 136 + c] = __float2bfloat16(acc);
    }
    __syncthreads();
    __nv_bfloat16* dst = g_t4r + (size_t)(n * Hh + h) * 14336;
    for (int i = tid; i < 112 * 16; i += 256) {
        int w = i >> 4, q = i & 15;
        *reinterpret_cast<uint4*>(dst + w * 128 + q * 8) =
            *reinterpret_cast<const uint4*>(ts + w * 136 + q * 8);
    }
}

// ---------------------------------------------------------------------------
// K8: t15 via 1-pass bf16 mma; B via ldsm4 j-pairs (7 per chunk)
// ---------------------------------------------------------------------------
__global__ void __launch_bounds__(256, 2) k_t15(float* __restrict__ out) {
    extern __shared__ __nv_bfloat16 smt[];
    __nv_bfloat16* sA = smt;               // [128 o][232]
    __nv_bfloat16* sB = smt + 128 * 232;   // [112 w][136]
    int h = blockIdx.x, n = blockIdx.y;
    int tid = threadIdx.x, lane = tid & 31, warp = tid >> 5;
    int g = warp >> 1;
    int h2 = (h + 2) % Hh;

    for (int i = tid; i < 128 * 28; i += 256) {
        int o = i / 28, q = i % 28;
        *reinterpret_cast<uint4*>(sA + o * 232 + q * 8) =
            *reinterpret_cast<const uint4*>(g_weffb + o * 224 + q * 8);
    }

    int qa_row = (lane & 7) + ((lane >> 3) & 1) * 8;
    int qa_col = (lane >> 4) * 8;
    int qb4_row = (lane & 7) + ((lane >> 4) & 1) * 8;
    int qb4_col = ((lane >> 3) & 1) * 8;
    u32 aP = smem_u32(sA), bP = smem_u32(sB);

    float acc[14][4];
    #pragma unroll
    for (int j = 0; j < 14; j++)
        #pragma unroll
        for (int c = 0; c < 4; c++) acc[j][c] = 0.f;

    for (int k = 0; k < 7; k++) {
        int r = h2 + 2 * k - 6;
        if (r < 0 || r >= Hh) continue;
        __syncthreads();
        const __nv_bfloat16* src = g_t4r + (size_t)(n * Hh + r) * 14336;
        for (int i = tid; i < 112 * 16; i += 256) {
            int w = i >> 4, q = i & 15;
            *reinterpret_cast<uint4*>(sB + w * 136 + q * 8) =
                *reinterpret_cast<const uint4*>(src + w * 128 + q * 8);
        }
        __syncthreads();
        #pragma unroll
        for (int chunk = 0; chunk < 2; chunk++) {
            u32 a0, a1, a2, a3;
            u32 aoff = (u32)(((warp * 16 + qa_row) * 232 + k * 32 + chunk * 16 + qa_col) * 2);
            ldsm4(a0, a1, a2, a3, aP + aoff);
            int bcol = g * 32 + chunk * 16;
            #pragma unroll
            for (int jp = 0; jp < 7; jp++) {     // j-pairs: rows [jp*16, jp*16+16)
                u32 b0, b1, b2, b3;
                u32 boff = (u32)(((jp * 16 + qb4_row) * 136 + bcol + qb4_col) * 2);
                ldsm4(b0, b1, b2, b3, bP + boff);
                mma16816(acc[2 * jp],     a0, a1, a2, a3, b0, b1);
                mma16816(acc[2 * jp + 1], a0, a1, a2, a3, b2, b3);
            }
        }
    }
    int r0 = lane >> 2, c0 = 2 * (lane & 3);
    float* ob = out + (size_t)n * CHW + (size_t)h * Ww;
    #pragma unroll
    for (int j = 0; j < 14; j++) {
        int o = warp * 16 + r0;
        int w = j * 8 + c0;
        ob[(size_t)o * HW + w]           = acc[j][0];
        ob[(size_t)o * HW + w + 1]       = acc[j][1];
        ob[(size_t)(o + 8) * HW + w]     = acc[j][2];
        ob[(size_t)(o + 8) * HW + w + 1] = acc[j][3];
    }
}

// ---------------------------------------------------------------------------
extern "C" void kernel_launch(void* const* d_in, const int* in_sizes, int n_in,
                              void* d_out, int out_size) {
    const float* x   = (const float*)d_in[0];
    const float* w3  = (const float*)d_in[1];
    const float* w4  = (const float*)d_in[2];
    const float* w9  = (const float*)d_in[3];
    const float* w10 = (const float*)d_in[4];
    const float* w15 = (const float*)d_in[5];
    float* out = (float*)d_out;

    const int SMEM_SILU = 116 * 129 * 4;                      // 59856
    const int SMEM_T5   = 4 * 128 * 72 * 2;                   // 73728
    const int SMEM_C3   = (132 * 136 + 128 * 136) * 2;        // 70720
    const int SMEM_T14  = (2 * 128 * 136 + 2 * 32 * 136) * 2; // 87040
    const int SMEM_T15  = (128 * 232 + 112 * 136) * 2;        // 89856
    cudaFuncSetAttribute(k_silu_t, cudaFuncAttributeMaxDynamicSharedMemorySize, SMEM_SILU);
    cudaFuncSetAttribute(k_t5,     cudaFuncAttributeMaxDynamicSharedMemorySize, SMEM_T5);
    cudaFuncSetAttribute(k_conv3,  cudaFuncAttributeMaxDynamicSharedMemorySize, SMEM_C3);
    cudaFuncSetAttribute(k_t14,    cudaFuncAttributeMaxDynamicSharedMemorySize, SMEM_T14);
    cudaFuncSetAttribute(k_t15,    cudaFuncAttributeMaxDynamicSharedMemorySize, SMEM_T15);

    // t15 (writes out) at profiled launch index 3; t14 accumulates after.
    k_silu_t<<< dim3(112, 8), 256, SMEM_SILU >>>(x, w3, w10, w15);  // + embedded prep
    k_conv3 <<< dim3(112, 8), 256, SMEM_C3 >>>();
    k_t4r   <<< dim3(112, 8), 256 >>>(w4);
    k_t15   <<< dim3(112, 8), 256, SMEM_T15 >>>(out);
    k_t5    <<< dim3(28, 8), 256, SMEM_T5 >>>(x);
    k_prep2 <<< 512, 256 >>>(w9);
    k_t14   <<< dim3(28, 8), 256, SMEM_T14 >>>(out);
}